// round 17
// baseline (speedup 1.0000x reference)
#include <cuda_runtime.h>
#include <math.h>

#define NN 10000
#define NE 160000
#define WSTR 256
#define TSTR 132
#define NTAB 8192
#define RMAX 5.0f

// ---------------- device scratch ----------------
__device__ float g_CG[615];
__device__ __align__(16) float g_t[(size_t)NN * TSTR];
__device__ float g_h1[(size_t)NN * 130];
__device__ float g_h2[(size_t)NN * 130];
__device__ float g_tab[3][(size_t)NTAB * WSTR];

// ---------------- CG init tables ----------------
__constant__ int c_cgPos[15] = {0,1,10,35,44,53,80,125,170,245,270,315,390,415,490};
__constant__ int c_cgL[15][3] = {{0,0,0},{0,1,1},{0,2,2},{1,0,1},{1,1,0},{1,1,1},{1,1,2},
  {1,2,1},{1,2,2},{2,0,2},{2,1,1},{2,1,2},{2,2,0},{2,2,1},{2,2,2}};

// ---------------- compile-time group descriptors ----------------
#define GARR(name, N, ...) \
  __device__ static constexpr int name(int p){ const int a[N]={__VA_ARGS__}; return a[p]; }

struct G1L0 { static constexpr int np=1, vout=32, nk=1, oo=0, gw=8;
  GARR(li,1, 0) GARR(fo,1, 0) GARR(mul,1, 8) GARR(cg,1, 0)
  GARR(yb,1, 0) GARR(nj,1, 1) GARR(wo,1, 0) GARR(uc,1, 0) };
struct G1L1 { static constexpr int np=1, vout=16, nk=3, oo=32, gw=8;
  GARR(li,1, 0) GARR(fo,1, 0) GARR(mul,1, 8) GARR(cg,1, 1)
  GARR(yb,1, 1) GARR(nj,1, 3) GARR(wo,1, 8) GARR(uc,1, 0) };
struct G1L2 { static constexpr int np=1, vout=10, nk=5, oo=80, gw=8;
  GARR(li,1, 0) GARR(fo,1, 0) GARR(mul,1, 8) GARR(cg,1, 10)
  GARR(yb,1, 4) GARR(nj,1, 5) GARR(wo,1, 16) GARR(uc,1, 0) };

struct G2L0 { static constexpr int np=3, vout=32, nk=1, oo=0, gw=58;
  GARR(li,3, 0,1,2) GARR(fo,3, 0,32,80) GARR(mul,3, 32,16,10)
  GARR(cg,3, 0,44,390) GARR(yb,3, 0,1,4) GARR(nj,3, 1,3,5)
  GARR(wo,3, 0,112,222) GARR(uc,3, 0,32,48) };
struct G2L1 { static constexpr int np=6, vout=16, nk=3, oo=32, gw=100;
  GARR(li,6, 0,1,1,1,2,2) GARR(fo,6, 0,32,32,32,80,80)
  GARR(mul,6, 32,16,16,16,10,10) GARR(cg,6, 1,35,53,125,270,415)
  GARR(yb,6, 1,0,1,4,1,4) GARR(nj,6, 3,1,3,5,3,5)
  GARR(wo,6, 32,96,128,160,202,232) GARR(uc,6, 0,32,48,64,80,90) };
struct G2L2 { static constexpr int np=6, vout=10, nk=5, oo=80, gw=94;
  GARR(li,6, 0,1,1,2,2,2) GARR(fo,6, 0,32,32,80,80,80)
  GARR(mul,6, 32,16,16,10,10,10) GARR(cg,6, 10,80,170,245,315,490)
  GARR(yb,6, 4,1,4,0,1,4) GARR(nj,6, 5,3,5,1,3,5)
  GARR(wo,6, 64,144,176,192,212,242) GARR(uc,6, 0,32,48,64,74,84) };

struct G3L0 { static constexpr int np=3, vout=1, nk=1, oo=0, gw=58;
  GARR(li,3, 0,1,2) GARR(fo,3, 0,32,80) GARR(mul,3, 32,16,10)
  GARR(cg,3, 0,44,390) GARR(yb,3, 0,1,4) GARR(nj,3, 1,3,5)
  GARR(wo,3, 0,32,48) GARR(uc,3, 0,32,48) };

// ---------------- vectorized global reductions ----------------
__device__ __forceinline__ void red4(float* p, float a, float b, float c, float d){
  asm volatile("red.global.add.v4.f32 [%0], {%1,%2,%3,%4};"
               :: "l"(p), "f"(a), "f"(b), "f"(c), "f"(d) : "memory");
}
__device__ __forceinline__ void red2(float* p, float a, float b){
  asm volatile("red.global.add.v2.f32 [%0], {%1,%2};"
               :: "l"(p), "f"(a), "f"(b) : "memory");
}

// ---------------- CG construction ----------------
__device__ double dfact_(int n){ double r=1.0; for (int i=2;i<=n;++i) r*=(double)i; return r; }

__device__ double cg_c(int j1,int m1,int j2,int m2,int j3,int m3){
  if (m1+m2 != m3) return 0.0;
  double pref = sqrt((2.0*j3+1.0)*dfact_(j1+j2-j3)*dfact_(j1-j2+j3)*dfact_(-j1+j2+j3)/dfact_(j1+j2+j3+1));
  pref *= sqrt(dfact_(j1+m1)*dfact_(j1-m1)*dfact_(j2+m2)*dfact_(j2-m2)*dfact_(j3+m3)*dfact_(j3-m3));
  int kmin = 0;
  if (j2-j3-m1 > kmin) kmin = j2-j3-m1;
  if (j1-j3+m2 > kmin) kmin = j1-j3+m2;
  int kmax = j1+j2-j3;
  if (j1-m1 < kmax) kmax = j1-m1;
  if (j2+m2 < kmax) kmax = j2+m2;
  double s = 0.0;
  for (int k=kmin; k<=kmax; ++k){
    double dn = dfact_(k)*dfact_(j1+j2-j3-k)*dfact_(j1-m1-k)*dfact_(j2+m2-k)*dfact_(j3-j2+m1+k)*dfact_(j3-j1-m2+k);
    s += ((k&1)? -1.0 : 1.0)/dn;
  }
  return pref*s;
}

__device__ void qmat_f(int l, float Qr[5][5], float Qi[5][5]){
  for (int a=0;a<5;++a) for (int b=0;b<5;++b){ Qr[a][b]=0.f; Qi[a][b]=0.f; }
  Qr[l][l] = 1.f;
  const float s2 = 0.70710678118654752f;
  for (int m=1;m<=l;++m){
    float sg = (m&1)? -1.f : 1.f;
    Qr[l+m][l+m] = sg*s2;
    Qr[l+m][l-m] = s2;
    Qi[l-m][l-m] = s2;
    Qi[l-m][l+m] = -sg*s2;
  }
}

__global__ void cg_init_kernel(){
  int bid = blockIdx.x, t = threadIdx.x;
  int l1=c_cgL[bid][0], l2=c_cgL[bid][1], l3=c_cgL[bid][2];
  int n1=2*l1+1, n2=2*l2+1, n3=2*l3+1;
  __shared__ float Csh[5][5];
  __shared__ float Q1r[5][5],Q1i[5][5],Q2r[5][5],Q2i[5][5],Q3r[5][5],Q3i[5][5];
  __shared__ float Kr[125], Ki[125];
  __shared__ float s_scale;
  __shared__ int   s_useIm;
  if (t==0){ qmat_f(l1,Q1r,Q1i); qmat_f(l2,Q2r,Q2i); qmat_f(l3,Q3r,Q3i); }
  if (t < n1*n2){
    int a=t/n2, b=t%n2;
    int m1=a-l1, m2=b-l2, m3=m1+m2;
    Csh[a][b] = (m3>=-l3 && m3<=l3) ? (float)cg_c(l1,m1,l2,m2,l3,m3) : 0.f;
  }
  __syncthreads();
  int nel = n1*n2*n3;
  if (t < nel){
    int i=t/(n2*n3), j=(t/n3)%n2, k=t%n3;
    float sr=0.f, si=0.f;
    for (int a=0;a<n1;++a)
      for (int b=0;b<n2;++b){
        float Cv = Csh[a][b];
        if (Cv != 0.f){
          int cc = l3 + (a-l1) + (b-l2);
          float p1r=Q1r[i][a], p1i=-Q1i[i][a];
          float p2r=Q2r[j][b], p2i=-Q2i[j][b];
          float ar=p1r*p2r - p1i*p2i, ai=p1r*p2i + p1i*p2r;
          sr += (ar*Q3r[k][cc] - ai*Q3i[k][cc])*Cv;
          si += (ar*Q3i[k][cc] + ai*Q3r[k][cc])*Cv;
        }
      }
    Kr[t]=sr; Ki[t]=si;
  }
  __syncthreads();
  if (t==0){
    float mR=0.f, mI=0.f;
    for (int q=0;q<nel;++q){ mR=fmaxf(mR,fabsf(Kr[q])); mI=fmaxf(mI,fabsf(Ki[q])); }
    int useIm = (mI > mR);
    float nrm=0.f;
    for (int q=0;q<nel;++q){ float v = useIm ? -Ki[q] : Kr[q]; nrm += v*v; }
    s_scale = sqrtf((float)n3)*rsqrtf(nrm);
    s_useIm = useIm;
  }
  __syncthreads();
  if (t < nel){
    float v = s_useIm ? -Ki[t] : Kr[t];
    g_CG[c_cgPos[bid] + t] = v * s_scale;
  }
}

// ---------------- zero scratch accumulator ----------------
__global__ void zero_t_kernel(){
  int i = blockIdx.x*256 + threadIdx.x;
  if (i < NN*TSTR) g_t[i] = 0.f;
}

// ---------------- radial weight TABLE build (16 rows/block for low latency) ----------------
template<int NOUT>
__global__ void tab_build_kernel(const float* __restrict__ W1,    // (10,100)
                                 const float* __restrict__ W2,    // (100,NOUT)
                                 int tab){
  __shared__ float sW1[1000];
  __shared__ float sHid[1600];
  __shared__ float sEmb[160];
  int t = threadIdx.x;
  int r0 = blockIdx.x*16;
  for (int i=t;i<1000;i+=256) sW1[i]=W1[i];
  __syncthreads();
  const float step = 5.0f/11.0f;
  const float pref = 1.14136f * 7.3890560989306495f * 3.1622776601683795f;
  const float hstep = RMAX/(float)(NTAB-1);
  if (t < 160){
    int el=t/10, b=t%10;
    float r = hstep*(float)(r0+el);
    float dd = (r - step*(float)(b+1))/step;
    float t1 = dd+1.f, t2 = 1.f-dd;
    float u1 = (t1>0.f)? expf(-1.f/t1) : 0.f;
    float u2 = (t2>0.f)? expf(-1.f/t2) : 0.f;
    sEmb[t] = pref*u1*u2;
  }
  __syncthreads();
  for (int i=t;i<1600;i+=256){
    int el=i/100, h=i%100;
    float a=0.f;
    #pragma unroll
    for (int b=0;b<10;++b) a += sEmb[el*10+b]*sW1[b*100+h];
    sHid[i] = a/(1.f+expf(-a));
  }
  __syncthreads();
  constexpr int NQ = (NOUT+31)/32;
  int warp = t>>5, lane = t&31;
  int eb = warp*2;
  float acc[2][NQ];
  #pragma unroll
  for (int a=0;a<2;++a)
    #pragma unroll
    for (int q=0;q<NQ;++q) acc[a][q]=0.f;
  #pragma unroll 2
  for (int h=0;h<100;++h){
    float wv[NQ];
    #pragma unroll
    for (int q=0;q<NQ;++q){
      int o = q*32 + lane;
      wv[q] = (o<NOUT)? W2[h*NOUT+o] : 0.f;
    }
    #pragma unroll
    for (int a=0;a<2;++a){
      float f = sHid[(eb+a)*100 + h];
      #pragma unroll
      for (int q=0;q<NQ;++q) acc[a][q] += f*wv[q];
    }
  }
  float* T = g_tab[tab];
  #pragma unroll
  for (int a=0;a<2;++a){
    size_t row = (size_t)(r0 + eb + a);
    #pragma unroll
    for (int q=0;q<NQ;++q){
      int o = q*32 + lane;
      if (o<NOUT) T[row*WSTR + o] = acc[a][q];
    }
  }
}

// ---------------- cooperative per-group weight staging from table ----------------
template<class G, int WP>
__device__ __forceinline__ void stage_w(float* __restrict__ sW,
                                        const float* __restrict__ T,
                                        const int* __restrict__ sI,
                                        const int* __restrict__ sI1,
                                        const float* __restrict__ sFr,
                                        int t){
  #pragma unroll
  for (int p=0;p<G::np;++p){
    const int M = G::mul(p);
    for (int idx=t; idx<64*M; idx+=64){
      int el = idx/M, u = idx-el*M;
      int o = G::wo(p)+u;
      float a = T[(size_t)sI[el]*WSTR + o];
      float b = T[(size_t)sI1[el]*WSTR + o];
      sW[el*WP + G::uc(p)+u] = a + sFr[el]*(b-a);
    }
  }
}

// ---------------- per-group tensor product + linear + scatter ----------------
template<class G>
__device__ __forceinline__ void run_group(const float* __restrict__ sFrow,
                                          const float (&Y)[9],
                                          const float* __restrict__ sCG,
                                          const float* __restrict__ myW,
                                          const float* __restrict__ lin,
                                          float* __restrict__ obase){
  constexpr int VOUT = G::vout, NK = G::nk;
  float acc[VOUT][NK];
  #pragma unroll
  for (int v=0;v<VOUT;++v)
    #pragma unroll
    for (int k=0;k<NK;++k) acc[v][k]=0.f;
  #pragma unroll
  for (int p=0;p<G::np;++p){
    const int ni = 2*G::li(p)+1;
    float B[5][NK];
    #pragma unroll
    for (int i=0;i<5;++i){
      if (i < ni){
        #pragma unroll
        for (int k=0;k<NK;++k){
          float b=0.f;
          #pragma unroll
          for (int j=0;j<5;++j)
            if (j < G::nj(p)) b += Y[G::yb(p)+j]*sCG[G::cg(p)+(i*G::nj(p)+j)*NK+k];
          B[i][k]=b;
        }
      }
    }
    const float* f = sFrow + G::fo(p);
    const float* L = lin + G::uc(p)*VOUT;
    #pragma unroll 4
    for (int u=0;u<G::mul(p);++u){
      float pw = myW[G::uc(p)+u];
      float m[NK];
      #pragma unroll
      for (int k=0;k<NK;++k){
        float a=0.f;
        #pragma unroll
        for (int i=0;i<5;++i)
          if (i < ni) a += f[u*ni+i]*B[i][k];
        m[k]=a*pw;
      }
      #pragma unroll
      for (int v=0;v<VOUT;++v){
        float lw = L[u*VOUT+v];
        #pragma unroll
        for (int k=0;k<NK;++k) acc[v][k] += lw*m[k];
      }
    }
  }
  constexpr int TOT = VOUT*NK;
  float* fl = &acc[0][0];
  if constexpr (TOT >= 4){
    #pragma unroll
    for (int i=0; i+3<TOT; i+=4)
      red4(obase+i, 0.25f*fl[i], 0.25f*fl[i+1], 0.25f*fl[i+2], 0.25f*fl[i+3]);
  }
  if constexpr ((TOT & 3) >= 2){
    constexpr int b = TOT & ~3;
    red2(obase+b, 0.25f*fl[b], 0.25f*fl[b+1]);
  }
  if constexpr (TOT & 1){
    atomicAdd(obase + (TOT-1), 0.25f*fl[TOT-1]);
  }
}

// ---------------- merged conv kernel with fused table interpolation ----------------
template<class GA, class GB, class GC, int NG, int FDIM, int FSTR, int WPM, int TAB>
__global__ void conv_merged_kernel(const float* __restrict__ evec,
                                   const int* __restrict__ src,
                                   const int* __restrict__ dst,
                                   const float* __restrict__ xin,
                                   int fsel,
                                   const float* __restrict__ linA,
                                   const float* __restrict__ linB,
                                   const float* __restrict__ linC){
  extern __shared__ float sm[];
  float* sF  = sm;                      // 64*FSTR
  float* sW  = sF + 64*FSTR;            // 64*WPM
  float* sCG = sW + 64*WPM;             // 615
  int*   sSrc = (int*)(sCG + 615);      // 64
  int*   sI   = sSrc + 64;              // 64
  int*   sI1  = sI + 64;                // 64
  float* sFr  = (float*)(sI1 + 64);     // 64

  int t = threadIdx.x;                  // 64 threads
  int e0 = blockIdx.x*64;
  const float* feats = (fsel==0)? xin : ((fsel==1)? g_h1 : g_h2);
  const float* T = g_tab[TAB];
  for (int i=t;i<615;i+=64) sCG[i]=g_CG[i];
  sSrc[t]=src[e0+t];

  int e = e0 + t;
  float vx=evec[3*e], vy=evec[3*e+1], vz=evec[3*e+2];
  float r2 = vx*vx+vy*vy+vz*vz;
  float rn = rsqrtf(r2);
  {
    float r = r2*rn;                    // |v|
    float p = fminf(r * ((float)(NTAB-1)/RMAX), (float)(NTAB-1));
    int i = (int)p;
    sI[t] = i;
    sI1[t] = (i+1 < NTAB)? i+1 : NTAB-1;
    sFr[t] = p - (float)i;
  }
  __syncthreads();
  for (int idx=t; idx<64*FDIM; idx+=64){
    int el=idx/FDIM, c=idx-el*FDIM;
    sF[el*FSTR+c] = feats[(size_t)sSrc[el]*FDIM + c];
  }
  float X=vx*rn, Yv=vy*rn, Z=vz*rn;
  const float c3=1.7320508075688772f, c15=3.872983346207417f, c5=2.23606797749979f;
  float Y[9] = {1.f, c3*Yv, c3*Z, c3*X,
                c15*X*Yv, c15*Yv*Z, 0.5f*c5*(3.f*Z*Z-1.f), c15*X*Z, 0.5f*c15*(X*X-Yv*Yv)};
  const float* myF  = sF + t*FSTR;
  int d = dst[e];
  float* tb = g_t + (size_t)d*TSTR;

  constexpr int WPA = (GA::gw)|1, WPB = (GB::gw)|1, WPC = (GC::gw)|1;
  stage_w<GA,WPA>(sW, T, sI, sI1, sFr, t);
  __syncthreads();
  run_group<GA>(myF, Y, sCG, sW + t*WPA, linA, tb + GA::oo);
  if constexpr (NG > 1){
    __syncthreads();
    stage_w<GB,WPB>(sW, T, sI, sI1, sFr, t);
    __syncthreads();
    run_group<GB>(myF, Y, sCG, sW + t*WPB, linB, tb + GB::oo);
  }
  if constexpr (NG > 2){
    __syncthreads();
    stage_w<GC,WPC>(sW, T, sI, sI1, sFr, t);
    __syncthreads();
    run_group<GC>(myF, Y, sCG, sW + t*WPC, linC, tb + GC::oo);
  }
}

// ---------------- node kernels ----------------
__global__ void post1_kernel(const float* __restrict__ x,
                             const float* __restrict__ sc1,
                             const float* __restrict__ gw){
  int n = blockIdx.x*128 + threadIdx.x;
  if (n >= NN) return;
  const float* tin = g_t + (size_t)n*TSTR;
  float xr[8];
  #pragma unroll
  for (int u=0;u<8;++u) xr[u]=x[n*8+u];
  float s0[32];
  #pragma unroll
  for (int v=0;v<32;++v){
    float a = tin[v];
    #pragma unroll
    for (int u=0;u<8;++u) a += xr[u]*sc1[u*32+v];
    s0[v]=a;
  }
  float g[26];
  #pragma unroll
  for (int j=0;j<26;++j){
    float a=0.f;
    #pragma unroll
    for (int v=0;v<32;++v) a += s0[v]*gw[v*26+j];
    g[j]=1.f/(1.f+expf(-a));
  }
  float* ho = g_h1 + (size_t)n*130;
  #pragma unroll
  for (int v=0;v<32;++v) ho[v] = s0[v]/(1.f+expf(-s0[v]));
  #pragma unroll
  for (int v=0;v<16;++v)
    #pragma unroll
    for (int k=0;k<3;++k) ho[32+v*3+k] = tin[32+v*3+k]*g[v];
  #pragma unroll
  for (int v=0;v<10;++v)
    #pragma unroll
    for (int k=0;k<5;++k) ho[80+v*5+k] = tin[80+v*5+k]*g[16+v];
}

__global__ void post2_kernel(const float* __restrict__ sc0,
                             const float* __restrict__ sc1m,
                             const float* __restrict__ sc2m,
                             const float* __restrict__ gw){
  int n = blockIdx.x*128 + threadIdx.x;
  if (n >= NN) return;
  const float* tin = g_t + (size_t)n*TSTR;
  const float* hp  = g_h1 + (size_t)n*130;
  float h0[32];
  #pragma unroll
  for (int u=0;u<32;++u) h0[u]=hp[u];
  float s0[32];
  #pragma unroll
  for (int v=0;v<32;++v){
    float a = tin[v];
    #pragma unroll
    for (int u=0;u<32;++u) a += h0[u]*sc0[u*32+v];
    s0[v]=a;
  }
  float g[26];
  #pragma unroll
  for (int j=0;j<26;++j){
    float a=0.f;
    #pragma unroll
    for (int v=0;v<32;++v) a += s0[v]*gw[v*26+j];
    g[j]=1.f/(1.f+expf(-a));
  }
  float* ho = g_h2 + (size_t)n*130;
  #pragma unroll
  for (int v=0;v<32;++v) ho[v] = s0[v]/(1.f+expf(-s0[v]));
  #pragma unroll
  for (int v=0;v<16;++v)
    #pragma unroll
    for (int k=0;k<3;++k){
      float a = tin[32+v*3+k];
      #pragma unroll
      for (int u=0;u<16;++u) a += hp[32+u*3+k]*sc1m[u*16+v];
      ho[32+v*3+k] = a*g[v];
    }
  #pragma unroll
  for (int v=0;v<10;++v)
    #pragma unroll
    for (int k=0;k<5;++k){
      float a = tin[80+v*5+k];
      #pragma unroll
      for (int u=0;u<10;++u) a += hp[80+u*5+k]*sc2m[u*10+v];
      ho[80+v*5+k] = a*g[16+v];
    }
}

__global__ void final_kernel(const float* __restrict__ sc3,
                             float* __restrict__ out){
  int n = blockIdx.x*128 + threadIdx.x;
  if (n >= NN) return;
  float a = g_t[(size_t)n*TSTR];
  const float* hp = g_h2 + (size_t)n*130;
  #pragma unroll
  for (int u=0;u<32;++u) a += hp[u]*sc3[u];
  out[n] = a;
}

// ---------------- launcher ----------------
static inline int conv_smem(int FSTR, int WPM){
  return 4*(64*FSTR + 64*WPM + 615 + 3*64 + 64);
}

extern "C" void kernel_launch(void* const* d_in, const int* in_sizes, int n_in,
                              void* d_out, int out_size){
  const float* x      = (const float*)d_in[0];
  const float* evec   = (const float*)d_in[1];
  const float* fc1w1  = (const float*)d_in[2];
  const float* fc1w2  = (const float*)d_in[3];
  const float* lin1l0 = (const float*)d_in[4];
  const float* lin1l1 = (const float*)d_in[5];
  const float* lin1l2 = (const float*)d_in[6];
  const float* sc1l0  = (const float*)d_in[7];
  const float* gate1  = (const float*)d_in[8];
  const float* fc2w1  = (const float*)d_in[9];
  const float* fc2w2  = (const float*)d_in[10];
  const float* lin2l0 = (const float*)d_in[11];
  const float* lin2l1 = (const float*)d_in[12];
  const float* lin2l2 = (const float*)d_in[13];
  const float* sc2l0  = (const float*)d_in[14];
  const float* sc2l1  = (const float*)d_in[15];
  const float* sc2l2  = (const float*)d_in[16];
  const float* gate2  = (const float*)d_in[17];
  const float* fc3w1  = (const float*)d_in[18];
  const float* fc3w2  = (const float*)d_in[19];
  const float* lin3l0 = (const float*)d_in[20];
  const float* sc3l0  = (const float*)d_in[21];
  const int*   esrc   = (const int*)d_in[22];
  const int*   edst   = (const int*)d_in[23];
  float* out = (float*)d_out;

  auto k1 = conv_merged_kernel<G1L0,G1L1,G1L2,3,8,9,9,0>;
  auto k2 = conv_merged_kernel<G2L0,G2L1,G2L2,3,130,131,101,1>;
  auto k3 = conv_merged_kernel<G3L0,G3L0,G3L0,1,130,131,59,2>;
  int s1 = conv_smem(9,9), s2 = conv_smem(131,101), s3 = conv_smem(131,59);
  cudaFuncSetAttribute(k1, cudaFuncAttributeMaxDynamicSharedMemorySize, s1);
  cudaFuncSetAttribute(k2, cudaFuncAttributeMaxDynamicSharedMemorySize, s2);
  cudaFuncSetAttribute(k3, cudaFuncAttributeMaxDynamicSharedMemorySize, s3);

  cg_init_kernel<<<15,128>>>();
  tab_build_kernel<24><<<NTAB/16,256>>>(fc1w1, fc1w2, 0);
  tab_build_kernel<252><<<NTAB/16,256>>>(fc2w1, fc2w2, 1);
  tab_build_kernel<58><<<NTAB/16,256>>>(fc3w1, fc3w2, 2);

  // ---- layer 1 ----
  zero_t_kernel<<<(NN*TSTR+255)/256,256>>>();
  k1<<<NE/64,64,s1>>>(evec, esrc, edst, x, 0, lin1l0, lin1l1, lin1l2);
  post1_kernel<<<(NN+127)/128,128>>>(x, sc1l0, gate1);

  // ---- layer 2 ----
  zero_t_kernel<<<(NN*TSTR+255)/256,256>>>();
  k2<<<NE/64,64,s2>>>(evec, esrc, edst, x, 1, lin2l0, lin2l1, lin2l2);
  post2_kernel<<<(NN+127)/128,128>>>(sc2l0, sc2l1, sc2l2, gate2);

  // ---- layer 3 ----
  zero_t_kernel<<<(NN*TSTR+255)/256,256>>>();
  k3<<<NE/64,64,s3>>>(evec, esrc, edst, x, 2, lin3l0, lin3l0, lin3l0);
  final_kernel<<<(NN+127)/128,128>>>(sc3l0, out);
}